// round 2
// baseline (speedup 1.0000x reference)
#include <cuda_runtime.h>
#include <stdint.h>
#include <math.h>

#define NTOK 16384
#define HD   4096
#define NE   64
#define NP   6
#define TK   8

#define WARPS    8
#define TPW      4                 // tokens per warp
#define TPB      (WARPS * TPW)     // 32 tokens per block
#define NTHREADS (WARPS * 32)      // 256
#define H4       (HD / 4)
#define HU       (HD / 4)          // 16B units per comp row = 1024
#define NITER    (HU / 32)         // 32

// smem: comp[NP*HD] | cent[NE*NP] | centn[NE] | proj[TPB*NP] | cpart[WARPS*NP] | cvec[NP]
#define SMEM_FLOATS (NP*HD + NE*NP + NE + TPB*NP + WARPS*NP + NP)
#define SMEM_BYTES  (SMEM_FLOATS * 4)

#define FMA2(acc, a, b) \
    asm("fma.rn.f32x2 %0, %1, %2, %0;" : "+l"(acc) : "l"(a), "l"(b))

__global__ void __launch_bounds__(NTHREADS, 2)
kdtree_router_kernel(const float* __restrict__ x,
                     const float* __restrict__ mean,
                     const float* __restrict__ comp,
                     const float* __restrict__ cent,
                     float* __restrict__ out)
{
    extern __shared__ float smem[];
    float* comp_s  = smem;                       // NP*HD
    float* cent_s  = comp_s + NP * HD;           // NE*NP
    float* centn_s = cent_s + NE * NP;           // NE
    float* proj_s  = centn_s + NE;               // TPB*NP
    float* cpart   = proj_s + TPB * NP;          // WARPS*NP
    float* cvec    = cpart + WARPS * NP;         // NP

    const int tid  = threadIdx.x;
    const int lane = tid & 31;
    const int warp = tid >> 5;

    // ---- load PCA components + centroids into smem ----
    {
        const float4* cg = (const float4*)comp;
        float4* cs = (float4*)comp_s;
        #pragma unroll
        for (int i = tid; i < NP * H4; i += NTHREADS) cs[i] = cg[i];
        for (int i = tid; i < NE * NP; i += NTHREADS) cent_s[i] = cent[i];
    }
    __syncthreads();

    // ---- per-block constants: cvec[p] = mean . comp[p]; centroid norms ----
    {
        float a0=0.f,a1=0.f,a2=0.f,a3=0.f,a4=0.f,a5=0.f;
        #pragma unroll
        for (int j = 0; j < HD / (WARPS * 32); j++) {
            int h = warp * (HD / WARPS) + lane + j * 32;
            float m = __ldg(mean + h);
            a0 += m * comp_s[0*HD + h];
            a1 += m * comp_s[1*HD + h];
            a2 += m * comp_s[2*HD + h];
            a3 += m * comp_s[3*HD + h];
            a4 += m * comp_s[4*HD + h];
            a5 += m * comp_s[5*HD + h];
        }
        #pragma unroll
        for (int o = 16; o > 0; o >>= 1) {
            a0 += __shfl_xor_sync(0xffffffffu, a0, o);
            a1 += __shfl_xor_sync(0xffffffffu, a1, o);
            a2 += __shfl_xor_sync(0xffffffffu, a2, o);
            a3 += __shfl_xor_sync(0xffffffffu, a3, o);
            a4 += __shfl_xor_sync(0xffffffffu, a4, o);
            a5 += __shfl_xor_sync(0xffffffffu, a5, o);
        }
        if (lane == 0) {
            cpart[warp*NP+0]=a0; cpart[warp*NP+1]=a1; cpart[warp*NP+2]=a2;
            cpart[warp*NP+3]=a3; cpart[warp*NP+4]=a4; cpart[warp*NP+5]=a5;
        }
        if (tid < NE) {
            float s = 0.f;
            #pragma unroll
            for (int p = 0; p < NP; p++) {
                float c = cent_s[tid*NP + p];
                s += c * c;
            }
            centn_s[tid] = s;
        }
    }
    __syncthreads();
    if (tid < NP) {
        float s = 0.f;
        #pragma unroll
        for (int w = 0; w < WARPS; w++) s += cpart[w*NP + tid];
        cvec[tid] = s;
    }
    __syncthreads();

    // ---- projection: warp handles 4 tokens, f32x2 FMAs, 1-iter LDG prefetch ----
    const int t0 = blockIdx.x * TPB + warp * TPW;
    const ulonglong2* xu0 = (const ulonglong2*)(x + (size_t)(t0 + 0) * HD);
    const ulonglong2* xu1 = (const ulonglong2*)(x + (size_t)(t0 + 1) * HD);
    const ulonglong2* xu2 = (const ulonglong2*)(x + (size_t)(t0 + 2) * HD);
    const ulonglong2* xu3 = (const ulonglong2*)(x + (size_t)(t0 + 3) * HD);
    const ulonglong2* cu  = (const ulonglong2*)comp_s;

    unsigned long long acc[TPW][NP];
    #pragma unroll
    for (int t = 0; t < TPW; t++)
        #pragma unroll
        for (int p = 0; p < NP; p++) acc[t][p] = 0ull;

    int i = lane;
    ulonglong2 n0 = __ldcs(xu0 + i);
    ulonglong2 n1 = __ldcs(xu1 + i);
    ulonglong2 n2 = __ldcs(xu2 + i);
    ulonglong2 n3 = __ldcs(xu3 + i);

    #pragma unroll 1
    for (int it = 0; it < NITER; ++it) {
        ulonglong2 v0 = n0, v1 = n1, v2 = n2, v3 = n3;
        int ip = i + 32;
        if (it < NITER - 1) {
            n0 = __ldcs(xu0 + ip);
            n1 = __ldcs(xu1 + ip);
            n2 = __ldcs(xu2 + ip);
            n3 = __ldcs(xu3 + ip);
        }
        ulonglong2 c0 = cu[0*HU + i];
        ulonglong2 c1 = cu[1*HU + i];
        ulonglong2 c2 = cu[2*HU + i];
        ulonglong2 c3 = cu[3*HU + i];
        ulonglong2 c4 = cu[4*HU + i];
        ulonglong2 c5 = cu[5*HU + i];
        i = ip;

        FMA2(acc[0][0], v0.x, c0.x); FMA2(acc[0][0], v0.y, c0.y);
        FMA2(acc[0][1], v0.x, c1.x); FMA2(acc[0][1], v0.y, c1.y);
        FMA2(acc[0][2], v0.x, c2.x); FMA2(acc[0][2], v0.y, c2.y);
        FMA2(acc[0][3], v0.x, c3.x); FMA2(acc[0][3], v0.y, c3.y);
        FMA2(acc[0][4], v0.x, c4.x); FMA2(acc[0][4], v0.y, c4.y);
        FMA2(acc[0][5], v0.x, c5.x); FMA2(acc[0][5], v0.y, c5.y);

        FMA2(acc[1][0], v1.x, c0.x); FMA2(acc[1][0], v1.y, c0.y);
        FMA2(acc[1][1], v1.x, c1.x); FMA2(acc[1][1], v1.y, c1.y);
        FMA2(acc[1][2], v1.x, c2.x); FMA2(acc[1][2], v1.y, c2.y);
        FMA2(acc[1][3], v1.x, c3.x); FMA2(acc[1][3], v1.y, c3.y);
        FMA2(acc[1][4], v1.x, c4.x); FMA2(acc[1][4], v1.y, c4.y);
        FMA2(acc[1][5], v1.x, c5.x); FMA2(acc[1][5], v1.y, c5.y);

        FMA2(acc[2][0], v2.x, c0.x); FMA2(acc[2][0], v2.y, c0.y);
        FMA2(acc[2][1], v2.x, c1.x); FMA2(acc[2][1], v2.y, c1.y);
        FMA2(acc[2][2], v2.x, c2.x); FMA2(acc[2][2], v2.y, c2.y);
        FMA2(acc[2][3], v2.x, c3.x); FMA2(acc[2][3], v2.y, c3.y);
        FMA2(acc[2][4], v2.x, c4.x); FMA2(acc[2][4], v2.y, c4.y);
        FMA2(acc[2][5], v2.x, c5.x); FMA2(acc[2][5], v2.y, c5.y);

        FMA2(acc[3][0], v3.x, c0.x); FMA2(acc[3][0], v3.y, c0.y);
        FMA2(acc[3][1], v3.x, c1.x); FMA2(acc[3][1], v3.y, c1.y);
        FMA2(acc[3][2], v3.x, c2.x); FMA2(acc[3][2], v3.y, c2.y);
        FMA2(acc[3][3], v3.x, c3.x); FMA2(acc[3][3], v3.y, c3.y);
        FMA2(acc[3][4], v3.x, c4.x); FMA2(acc[3][4], v3.y, c4.y);
        FMA2(acc[3][5], v3.x, c5.x); FMA2(acc[3][5], v3.y, c5.y);
    }

    // ---- reduce across warp, write proj (mean-corrected) to smem ----
    #pragma unroll
    for (int t = 0; t < TPW; t++) {
        #pragma unroll
        for (int p = 0; p < NP; p++) {
            unsigned long long v = acc[t][p];
            float s = __uint_as_float((unsigned)(v & 0xffffffffull)) +
                      __uint_as_float((unsigned)(v >> 32));
            #pragma unroll
            for (int o = 16; o > 0; o >>= 1)
                s += __shfl_xor_sync(0xffffffffu, s, o);
            if (lane == 0)
                proj_s[(warp*TPW + t)*NP + p] = s - cvec[p];
        }
    }
    __syncthreads();

    // ---- epilogue: distances, softmax over 64, top-8 ----
    float* out_idx = out;
    float* out_tp  = out + (size_t)NTOK * TK;
    float* out_pr  = out + 2 * (size_t)NTOK * TK;

    #pragma unroll 1
    for (int t = 0; t < TPW; t++) {
        const int tok = blockIdx.x * TPB + warp * TPW + t;
        float pr[NP];
        #pragma unroll
        for (int p = 0; p < NP; p++) pr[p] = proj_s[(warp*TPW + t)*NP + p];
        float pn = 0.f;
        #pragma unroll
        for (int p = 0; p < NP; p++) pn += pr[p] * pr[p];

        const int e0 = lane, e1 = lane + 32;
        float dot0 = 0.f, dot1 = 0.f;
        #pragma unroll
        for (int p = 0; p < NP; p++) {
            dot0 += pr[p] * cent_s[e0*NP + p];
            dot1 += pr[p] * cent_s[e1*NP + p];
        }
        float d20 = pn - 2.f*dot0 + centn_s[e0];
        float d21 = pn - 2.f*dot1 + centn_s[e1];
        float s0 = -sqrtf(fmaxf(d20, 0.f));
        float s1 = -sqrtf(fmaxf(d21, 0.f));

        // softmax over 64
        float m = fmaxf(s0, s1);
        #pragma unroll
        for (int o = 16; o > 0; o >>= 1)
            m = fmaxf(m, __shfl_xor_sync(0xffffffffu, m, o));
        float ex0 = expf(s0 - m);
        float ex1 = expf(s1 - m);
        float sum = ex0 + ex1;
        #pragma unroll
        for (int o = 16; o > 0; o >>= 1)
            sum += __shfl_xor_sync(0xffffffffu, sum, o);
        float p0 = ex0 / sum;
        float p1 = ex1 / sum;

        out_pr[(size_t)tok*NE + e0] = p0;
        out_pr[(size_t)tok*NE + e1] = p1;

        // top-8 via 8-round warp argmax; tie-break = lower index (jax.lax.top_k)
        unsigned long long k0 = ((unsigned long long)__float_as_uint(p0) << 32) | (unsigned)(NE-1 - e0);
        unsigned long long k1 = ((unsigned long long)__float_as_uint(p1) << 32) | (unsigned)(NE-1 - e1);
        float tsum = 0.f, myp = 0.f;
        int myi = 0;
        #pragma unroll
        for (int r = 0; r < TK; r++) {
            unsigned long long b = (k0 > k1) ? k0 : k1;
            #pragma unroll
            for (int o = 16; o > 0; o >>= 1) {
                unsigned long long v = __shfl_xor_sync(0xffffffffu, b, o);
                if (v > b) b = v;
            }
            int idx = NE-1 - (int)(b & 0xffull);
            float pv = __uint_as_float((unsigned)(b >> 32));
            tsum += pv;
            if (lane == r) { myp = pv; myi = idx; }
            if (idx == e0) k0 = 0ull;
            if (idx == e1) k1 = 0ull;
        }
        if (lane < TK) {
            out_idx[(size_t)tok*TK + lane] = (float)myi;
            out_tp [(size_t)tok*TK + lane] = myp / tsum;
        }
    }
}

extern "C" void kernel_launch(void* const* d_in, const int* in_sizes, int n_in,
                              void* d_out, int out_size)
{
    const float* x    = (const float*)d_in[0];
    const float* mean = (const float*)d_in[1];
    const float* comp = (const float*)d_in[2];
    const float* cent = (const float*)d_in[3];
    float* out = (float*)d_out;

    cudaFuncSetAttribute(kdtree_router_kernel,
                         cudaFuncAttributeMaxDynamicSharedMemorySize, SMEM_BYTES);
    kdtree_router_kernel<<<NTOK / TPB, NTHREADS, SMEM_BYTES>>>(x, mean, comp, cent, out);
}

// round 3
// speedup vs baseline: 1.0227x; 1.0227x over previous
#include <cuda_runtime.h>
#include <cuda.h>
#include <stdint.h>
#include <math.h>

#define NTOK 16384
#define HD   4096
#define NE   64
#define NP   6
#define TK   8

#define CWARPS   16                // consumer warps
#define TPW      4                 // tokens per consumer warp
#define TPB      (CWARPS * TPW)    // 64 tokens per block
#define NTHREADS ((CWARPS + 1) * 32)  // 544: 16 consumer warps + 1 producer warp
#define PROD_WARP CWARPS

#define CHUNK_F   128              // floats per token per chunk
#define CHUNK_B   (CHUNK_F * 4)    // 512 bytes
#define NCHUNK    (HD / CHUNK_F)   // 32
#define STAGES    3
#define STAGE_BYTES (TPB * CHUNK_B)   // 32768

// smem byte offsets
#define XS_OFF     0
#define COMP_OFF   (XS_OFF + STAGES * STAGE_BYTES)        // 98304
#define CENT_OFF   (COMP_OFF + NP * HD * 4)               // +98304
#define CENTN_OFF  (CENT_OFF + NE * NP * 4)
#define CPART_OFF  (CENTN_OFF + NE * 4)
#define CVEC_OFF   (CPART_OFF + CWARPS * NP * 4)
#define MBAR_OFF   (CVEC_OFF + 32)                        // 8-aligned
#define SMEM_BYTES (MBAR_OFF + 64)

#define FMA2(acc, a, b) \
    asm("fma.rn.f32x2 %0, %1, %2, %0;" : "+l"(acc) : "l"(a), "l"(b))

__device__ __forceinline__ uint32_t smem_u32(const void* p) {
    uint32_t a;
    asm("{ .reg .u64 t; cvta.to.shared.u64 t, %1; cvt.u32.u64 %0, t; }" : "=r"(a) : "l"(p));
    return a;
}

#define MBAR_INIT(addr, cnt) \
    asm volatile("mbarrier.init.shared.b64 [%0], %1;" :: "r"(addr), "r"(cnt) : "memory")
#define MBAR_EXPECT_TX(addr, bytes) \
    asm volatile("mbarrier.arrive.expect_tx.shared.b64 _, [%0], %1;" :: "r"(addr), "r"(bytes) : "memory")
#define MBAR_ARRIVE(addr) \
    asm volatile("mbarrier.arrive.shared.b64 _, [%0];" :: "r"(addr) : "memory")
#define MBAR_WAIT(addr, parity) do {                                             \
    asm volatile("{\n\t.reg .pred P;\n"                                          \
        "W_%=:\n\tmbarrier.try_wait.parity.acquire.cta.shared::cta.b64 P, [%0], %1, 0x989680;\n" \
        "\t@P bra D_%=;\n\tbra W_%=;\nD_%=:\n\t}"                                \
        :: "r"(addr), "r"(parity) : "memory"); } while (0)

__device__ __forceinline__ void tma2d(uint32_t dst, const CUtensorMap* m,
                                      int cx, int cy, uint32_t mbar) {
    asm volatile(
        "cp.async.bulk.tensor.2d.shared::cta.global.tile.mbarrier::complete_tx::bytes "
        "[%0], [%1, {%2, %3}], [%4];"
        :: "r"(dst), "l"(m), "r"(cx), "r"(cy), "r"(mbar) : "memory");
}

__global__ void __launch_bounds__(NTHREADS, 1)
kdtree_router_kernel(const float* __restrict__ mean,
                     const float* __restrict__ comp,
                     const float* __restrict__ cent,
                     float* __restrict__ out,
                     const __grid_constant__ CUtensorMap tmap)
{
    extern __shared__ __align__(1024) char smem_c[];
    float* comp_s  = (float*)(smem_c + COMP_OFF);
    float* cent_s  = (float*)(smem_c + CENT_OFF);
    float* centn_s = (float*)(smem_c + CENTN_OFF);
    float* cpart   = (float*)(smem_c + CPART_OFF);
    float* cvec    = (float*)(smem_c + CVEC_OFF);
    const uint32_t mb = smem_u32(smem_c + MBAR_OFF);
    const uint32_t xs = smem_u32(smem_c + XS_OFF);

    const int tid  = threadIdx.x;
    const int lane = tid & 31;
    const int warp = tid >> 5;

    // ---- init mbarriers (full[3] then empty[3]) ----
    if (tid == 0) {
        #pragma unroll
        for (int s = 0; s < STAGES; s++) {
            MBAR_INIT(mb + s * 8, 1);              // full: 1 arrive (expect_tx)
            MBAR_INIT(mb + 24 + s * 8, CWARPS);    // empty: 16 warp arrivals
        }
    }
    __syncthreads();

    // ---- producer prefill: chunks 0..2 (fresh empties, no wait needed) ----
    if (warp == PROD_WARP && lane == 0) {
        #pragma unroll
        for (int c = 0; c < STAGES; c++) {
            MBAR_EXPECT_TX(mb + c * 8, (uint32_t)STAGE_BYTES);
            tma2d(xs + c * STAGE_BYTES, &tmap, c * CHUNK_F, blockIdx.x * TPB, mb + c * 8);
        }
    }

    // ---- load PCA components + centroids into smem (overlaps TMA) ----
    {
        const float4* cg = (const float4*)comp;
        float4* cs = (float4*)comp_s;
        for (int i = tid; i < NP * HD / 4; i += NTHREADS) cs[i] = cg[i];
        for (int i = tid; i < NE * NP; i += NTHREADS) cent_s[i] = cent[i];
    }
    __syncthreads();

    // ---- per-block constants: cvec[p] = mean . comp[p]; centroid norms ----
    if (warp < CWARPS) {
        float a0=0.f,a1=0.f,a2=0.f,a3=0.f,a4=0.f,a5=0.f;
        #pragma unroll
        for (int j = 0; j < HD / (CWARPS * 32); j++) {
            int h = warp * (HD / CWARPS) + lane + j * 32;
            float m = __ldg(mean + h);
            a0 += m * comp_s[0*HD + h];
            a1 += m * comp_s[1*HD + h];
            a2 += m * comp_s[2*HD + h];
            a3 += m * comp_s[3*HD + h];
            a4 += m * comp_s[4*HD + h];
            a5 += m * comp_s[5*HD + h];
        }
        #pragma unroll
        for (int o = 16; o > 0; o >>= 1) {
            a0 += __shfl_xor_sync(0xffffffffu, a0, o);
            a1 += __shfl_xor_sync(0xffffffffu, a1, o);
            a2 += __shfl_xor_sync(0xffffffffu, a2, o);
            a3 += __shfl_xor_sync(0xffffffffu, a3, o);
            a4 += __shfl_xor_sync(0xffffffffu, a4, o);
            a5 += __shfl_xor_sync(0xffffffffu, a5, o);
        }
        if (lane == 0) {
            cpart[warp*NP+0]=a0; cpart[warp*NP+1]=a1; cpart[warp*NP+2]=a2;
            cpart[warp*NP+3]=a3; cpart[warp*NP+4]=a4; cpart[warp*NP+5]=a5;
        }
        if (tid < NE) {
            float s = 0.f;
            #pragma unroll
            for (int p = 0; p < NP; p++) { float c = cent_s[tid*NP + p]; s += c * c; }
            centn_s[tid] = s;
        }
    }
    __syncthreads();
    if (tid < NP) {
        float s = 0.f;
        #pragma unroll
        for (int w = 0; w < CWARPS; w++) s += cpart[w*NP + tid];
        cvec[tid] = s;
    }
    __syncthreads();

    if (warp == PROD_WARP) {
        // ================= producer: chunks 3..NCHUNK-1 =================
        if (lane == 0) {
            #pragma unroll 1
            for (int c = STAGES; c < NCHUNK; c++) {
                int u = c / STAGES;
                int s = c - u * STAGES;
                uint32_t fullb  = mb + s * 8;
                uint32_t emptyb = mb + 24 + s * 8;
                MBAR_WAIT(emptyb, (u & 1) ^ 1);
                MBAR_EXPECT_TX(fullb, (uint32_t)STAGE_BYTES);
                tma2d(xs + s * STAGE_BYTES, &tmap, c * CHUNK_F, blockIdx.x * TPB, fullb);
            }
        }
        return;
    }

    // ================= consumers: 16 warps x 4 tokens =================
    const ulonglong2* cu = (const ulonglong2*)comp_s;   // 1024 units per row

    unsigned long long acc[TPW][NP];
    #pragma unroll
    for (int t = 0; t < TPW; t++)
        #pragma unroll
        for (int p = 0; p < NP; p++) acc[t][p] = 0ull;

    #pragma unroll 1
    for (int c = 0; c < NCHUNK; c++) {
        int u = c / STAGES;
        int s = c - u * STAGES;
        uint32_t fullb  = mb + s * 8;
        uint32_t emptyb = mb + 24 + s * 8;
        MBAR_WAIT(fullb, u & 1);

        const ulonglong2* xp = (const ulonglong2*)
            (smem_c + XS_OFF + s * STAGE_BYTES + (warp * TPW) * CHUNK_B + lane * 16);
        ulonglong2 v0 = xp[0];
        ulonglong2 v1 = xp[32];
        ulonglong2 v2 = xp[64];
        ulonglong2 v3 = xp[96];

        int idx = c * 32 + lane;
        ulonglong2 c0 = cu[0*1024 + idx];
        ulonglong2 c1 = cu[1*1024 + idx];
        ulonglong2 c2 = cu[2*1024 + idx];
        ulonglong2 c3 = cu[3*1024 + idx];
        ulonglong2 c4 = cu[4*1024 + idx];
        ulonglong2 c5 = cu[5*1024 + idx];

        FMA2(acc[0][0], v0.x, c0.x); FMA2(acc[0][0], v0.y, c0.y);
        FMA2(acc[0][1], v0.x, c1.x); FMA2(acc[0][1], v0.y, c1.y);
        FMA2(acc[0][2], v0.x, c2.x); FMA2(acc[0][2], v0.y, c2.y);
        FMA2(acc[0][3], v0.x, c3.x); FMA2(acc[0][3], v0.y, c3.y);
        FMA2(acc[0][4], v0.x, c4.x); FMA2(acc[0][4], v0.y, c4.y);
        FMA2(acc[0][5], v0.x, c5.x); FMA2(acc[0][5], v0.y, c5.y);

        FMA2(acc[1][0], v1.x, c0.x); FMA2(acc[1][0], v1.y, c0.y);
        FMA2(acc[1][1], v1.x, c1.x); FMA2(acc[1][1], v1.y, c1.y);
        FMA2(acc[1][2], v1.x, c2.x); FMA2(acc[1][2], v1.y, c2.y);
        FMA2(acc[1][3], v1.x, c3.x); FMA2(acc[1][3], v1.y, c3.y);
        FMA2(acc[1][4], v1.x, c4.x); FMA2(acc[1][4], v1.y, c4.y);
        FMA2(acc[1][5], v1.x, c5.x); FMA2(acc[1][5], v1.y, c5.y);

        FMA2(acc[2][0], v2.x, c0.x); FMA2(acc[2][0], v2.y, c0.y);
        FMA2(acc[2][1], v2.x, c1.x); FMA2(acc[2][1], v2.y, c1.y);
        FMA2(acc[2][2], v2.x, c2.x); FMA2(acc[2][2], v2.y, c2.y);
        FMA2(acc[2][3], v2.x, c3.x); FMA2(acc[2][3], v2.y, c3.y);
        FMA2(acc[2][4], v2.x, c4.x); FMA2(acc[2][4], v2.y, c4.y);
        FMA2(acc[2][5], v2.x, c5.x); FMA2(acc[2][5], v2.y, c5.y);

        FMA2(acc[3][0], v3.x, c0.x); FMA2(acc[3][0], v3.y, c0.y);
        FMA2(acc[3][1], v3.x, c1.x); FMA2(acc[3][1], v3.y, c1.y);
        FMA2(acc[3][2], v3.x, c2.x); FMA2(acc[3][2], v3.y, c2.y);
        FMA2(acc[3][3], v3.x, c3.x); FMA2(acc[3][3], v3.y, c3.y);
        FMA2(acc[3][4], v3.x, c4.x); FMA2(acc[3][4], v3.y, c4.y);
        FMA2(acc[3][5], v3.x, c5.x); FMA2(acc[3][5], v3.y, c5.y);

        __syncwarp();
        if (lane == 0) MBAR_ARRIVE(emptyb);
    }

    // ---- reduce across lanes (butterfly leaves sum in ALL lanes) ----
    float pr[TPW][NP];
    #pragma unroll
    for (int t = 0; t < TPW; t++) {
        #pragma unroll
        for (int p = 0; p < NP; p++) {
            unsigned long long v = acc[t][p];
            float s = __uint_as_float((unsigned)(v & 0xffffffffull)) +
                      __uint_as_float((unsigned)(v >> 32));
            #pragma unroll
            for (int o = 16; o > 0; o >>= 1)
                s += __shfl_xor_sync(0xffffffffu, s, o);
            pr[t][p] = s - cvec[p];
        }
    }

    // ---- epilogue: distances, softmax over 64, top-8 ----
    float* out_idx = out;
    float* out_tp  = out + (size_t)NTOK * TK;
    float* out_pr  = out + 2 * (size_t)NTOK * TK;

    #pragma unroll 1
    for (int t = 0; t < TPW; t++) {
        const int tok = blockIdx.x * TPB + warp * TPW + t;
        float pn = 0.f;
        #pragma unroll
        for (int p = 0; p < NP; p++) pn += pr[t][p] * pr[t][p];

        const int e0 = lane, e1 = lane + 32;
        float dot0 = 0.f, dot1 = 0.f;
        #pragma unroll
        for (int p = 0; p < NP; p++) {
            dot0 += pr[t][p] * cent_s[e0*NP + p];
            dot1 += pr[t][p] * cent_s[e1*NP + p];
        }
        float d20 = pn - 2.f*dot0 + centn_s[e0];
        float d21 = pn - 2.f*dot1 + centn_s[e1];
        float s0 = -sqrtf(fmaxf(d20, 0.f));
        float s1 = -sqrtf(fmaxf(d21, 0.f));

        float m = fmaxf(s0, s1);
        #pragma unroll
        for (int o = 16; o > 0; o >>= 1)
            m = fmaxf(m, __shfl_xor_sync(0xffffffffu, m, o));
        float ex0 = expf(s0 - m);
        float ex1 = expf(s1 - m);
        float sum = ex0 + ex1;
        #pragma unroll
        for (int o = 16; o > 0; o >>= 1)
            sum += __shfl_xor_sync(0xffffffffu, sum, o);
        float p0 = ex0 / sum;
        float p1 = ex1 / sum;

        out_pr[(size_t)tok*NE + e0] = p0;
        out_pr[(size_t)tok*NE + e1] = p1;

        unsigned long long k0 = ((unsigned long long)__float_as_uint(p0) << 32) | (unsigned)(NE-1 - e0);
        unsigned long long k1 = ((unsigned long long)__float_as_uint(p1) << 32) | (unsigned)(NE-1 - e1);
        float tsum = 0.f, myp = 0.f;
        int myi = 0;
        #pragma unroll
        for (int r = 0; r < TK; r++) {
            unsigned long long b = (k0 > k1) ? k0 : k1;
            #pragma unroll
            for (int o = 16; o > 0; o >>= 1) {
                unsigned long long v = __shfl_xor_sync(0xffffffffu, b, o);
                if (v > b) b = v;
            }
            int idx = NE-1 - (int)(b & 0xffull);
            float pv = __uint_as_float((unsigned)(b >> 32));
            tsum += pv;
            if (lane == r) { myp = pv; myi = idx; }
            if (idx == e0) k0 = 0ull;
            if (idx == e1) k1 = 0ull;
        }
        if (lane < TK) {
            out_idx[(size_t)tok*TK + lane] = (float)myi;
            out_tp [(size_t)tok*TK + lane] = myp / tsum;
        }
    }
}

typedef CUresult (*EncodeTiledFn)(
    CUtensorMap*, CUtensorMapDataType, cuuint32_t, void*,
    const cuuint64_t*, const cuuint64_t*, const cuuint32_t*, const cuuint32_t*,
    CUtensorMapInterleave, CUtensorMapSwizzle, CUtensorMapL2promotion,
    CUtensorMapFloatOOBfill);

extern "C" void kernel_launch(void* const* d_in, const int* in_sizes, int n_in,
                              void* d_out, int out_size)
{
    const float* x    = (const float*)d_in[0];
    const float* mean = (const float*)d_in[1];
    const float* comp = (const float*)d_in[2];
    const float* cent = (const float*)d_in[3];
    float* out = (float*)d_out;

    void* fn = nullptr;
    cudaDriverEntryPointQueryResult qres;
    cudaGetDriverEntryPointByVersion("cuTensorMapEncodeTiled", &fn, 12000,
                                     cudaEnableDefault, &qres);

    CUtensorMap tmap;
    cuuint64_t gdim[2] = {HD, NTOK};
    cuuint64_t gstr[1] = {HD * sizeof(float)};
    cuuint32_t box[2]  = {CHUNK_F, TPB};
    cuuint32_t est[2]  = {1, 1};
    ((EncodeTiledFn)fn)(&tmap, CU_TENSOR_MAP_DATA_TYPE_FLOAT32, 2, (void*)x,
                        gdim, gstr, box, est,
                        CU_TENSOR_MAP_INTERLEAVE_NONE, CU_TENSOR_MAP_SWIZZLE_NONE,
                        CU_TENSOR_MAP_L2_PROMOTION_L2_128B,
                        CU_TENSOR_MAP_FLOAT_OOB_FILL_NONE);

    cudaFuncSetAttribute(kdtree_router_kernel,
                         cudaFuncAttributeMaxDynamicSharedMemorySize, SMEM_BYTES);
    kdtree_router_kernel<<<NTOK / TPB, NTHREADS, SMEM_BYTES>>>(mean, comp, cent, out, tmap);
}

// round 4
// speedup vs baseline: 1.1243x; 1.0994x over previous
#include <cuda_runtime.h>
#include <stdint.h>
#include <math.h>

#define NTOK 16384
#define HD   4096
#define NE   64
#define NP   6
#define TK   8

#define CWARPS   16                     // consumer warps (one 256-col slice each)
#define NTHREADS ((CWARPS + 1) * 32)    // 544: +1 producer warp
#define PROD_WARP CWARPS
#define TPB      64                     // tokens per block
#define SLICE    (HD / CWARPS)          // 256 columns per warp

#define STAGE_TOK   4
#define STAGE_BYTES (STAGE_TOK * HD * 4)   // 65536
#define NCHUNK      (TPB / STAGE_TOK)      // 16
#define STAGES      2

// smem byte offsets
#define XS_OFF    0
#define PART_OFF  (XS_OFF + STAGES * STAGE_BYTES)          // 131072
#define PART_SZ   ((TPB + 1) * NP * 32 * 4)                // 49920 (token 64 = mean proj)
#define CENT_OFF  (PART_OFF + PART_SZ)
#define CENTN_OFF (CENT_OFF + NE * NP * 4)
#define MBAR_OFF  ((CENTN_OFF + NE * 4 + 15) & ~15)
#define SMEM_BYTES (MBAR_OFF + 64)

#define FMA2(acc, a, b) \
    asm("fma.rn.f32x2 %0, %1, %2, %0;" : "+l"(acc) : "l"(a), "l"(b))
#define ADD2(d, a, b) \
    asm("add.rn.f32x2 %0, %1, %2;" : "=l"(d) : "l"(a), "l"(b))

__device__ __forceinline__ uint32_t smem_u32(const void* p) {
    uint32_t a;
    asm("{ .reg .u64 t; cvta.to.shared.u64 t, %1; cvt.u32.u64 %0, t; }" : "=r"(a) : "l"(p));
    return a;
}

#define MBAR_INIT(addr, cnt) \
    asm volatile("mbarrier.init.shared.b64 [%0], %1;" :: "r"(addr), "r"(cnt) : "memory")
#define MBAR_EXPECT_TX(addr, bytes) \
    asm volatile("mbarrier.arrive.expect_tx.shared.b64 _, [%0], %1;" :: "r"(addr), "r"(bytes) : "memory")
#define MBAR_ARRIVE(addr) \
    asm volatile("mbarrier.arrive.shared.b64 _, [%0];" :: "r"(addr) : "memory")
#define MBAR_WAIT(addr, parity) do {                                             \
    asm volatile("{\n\t.reg .pred P;\n"                                          \
        "W_%=:\n\tmbarrier.try_wait.parity.acquire.cta.shared::cta.b64 P, [%0], %1, 0x989680;\n" \
        "\t@P bra D_%=;\n\tbra W_%=;\nD_%=:\n\t}"                                \
        :: "r"(addr), "r"(parity) : "memory"); } while (0)

// plain contiguous bulk copy: gmem -> smem, completes on mbarrier
__device__ __forceinline__ void bulk_g2s(uint32_t dst, const void* src,
                                         uint32_t bytes, uint32_t mbar) {
    asm volatile(
        "cp.async.bulk.shared::cta.global.mbarrier::complete_tx::bytes "
        "[%0], [%1], %2, [%3];"
        :: "r"(dst), "l"(src), "r"(bytes), "r"(mbar) : "memory");
}

__global__ void __launch_bounds__(NTHREADS, 1)
kdtree_router_kernel(const float* __restrict__ x,
                     const float* __restrict__ mean,
                     const float* __restrict__ comp,
                     const float* __restrict__ cent,
                     float* __restrict__ out)
{
    extern __shared__ __align__(1024) char smem_c[];
    float* part    = (float*)(smem_c + PART_OFF);   // [(TPB+1)*NP][32]
    float* cent_s  = (float*)(smem_c + CENT_OFF);
    float* centn_s = (float*)(smem_c + CENTN_OFF);
    const uint32_t mb = smem_u32(smem_c + MBAR_OFF);
    const uint32_t xs = smem_u32(smem_c + XS_OFF);

    const int tid  = threadIdx.x;
    const int lane = tid & 31;
    const int warp = tid >> 5;

    if (tid == 0) {
        #pragma unroll
        for (int s = 0; s < STAGES; s++) {
            MBAR_INIT(mb + s * 8, 1);               // full: expect_tx only
            MBAR_INIT(mb + 16 + s * 8, CWARPS);     // empty: 16 warp arrivals
        }
    }
    // centroids
    for (int i = tid; i < NE * NP; i += NTHREADS) cent_s[i] = cent[i];
    __syncthreads();

    const char* xbase = (const char*)x + (size_t)blockIdx.x * TPB * HD * 4;

    if (warp == PROD_WARP) {
        // ======================= producer =======================
        if (lane == 0) {
            #pragma unroll
            for (int c = 0; c < STAGES; c++) {
                MBAR_EXPECT_TX(mb + c * 8, (uint32_t)STAGE_BYTES);
                bulk_g2s(xs + c * STAGE_BYTES, xbase + (size_t)c * STAGE_BYTES,
                         STAGE_BYTES, mb + c * 8);
            }
            #pragma unroll 1
            for (int c = STAGES; c < NCHUNK; c++) {
                int s = c & 1, u = c >> 1;
                MBAR_WAIT(mb + 16 + s * 8, (u & 1) ^ 1);
                MBAR_EXPECT_TX(mb + s * 8, (uint32_t)STAGE_BYTES);
                bulk_g2s(xs + s * STAGE_BYTES, xbase + (size_t)c * STAGE_BYTES,
                         STAGE_BYTES, mb + s * 8);
            }
        }
        __syncthreads();   // match consumers' pre-epilogue barrier
        return;
    }

    // ======================= consumers =======================
    // comp slice -> registers: lane holds cols {4l..4l+3} and {128+4l..128+4l+3}
    ulonglong2 cA[NP], cB[NP];
    {
        const ulonglong2* cp0 = (const ulonglong2*)(comp + warp * SLICE);
        #pragma unroll
        for (int p = 0; p < NP; p++) {
            cA[p] = cp0[(size_t)p * (HD/4) + lane];
            cB[p] = cp0[(size_t)p * (HD/4) + lane + 32];
        }
    }

    // mean projection partials (pseudo-token TPB), same reduce path as tokens
    {
        const ulonglong2* mp = (const ulonglong2*)(mean + warp * SLICE);
        ulonglong2 ma = mp[lane], mbv = mp[lane + 32];
        unsigned long long acc[NP];
        #pragma unroll
        for (int p = 0; p < NP; p++) {
            acc[p] = 0ull;
            FMA2(acc[p], ma.x,  cA[p].x); FMA2(acc[p], ma.y,  cA[p].y);
            FMA2(acc[p], mbv.x, cB[p].x); FMA2(acc[p], mbv.y, cB[p].y);
        }
        unsigned long long u[3];
        #pragma unroll
        for (int j = 0; j < 3; j++) {
            float f0 = __uint_as_float((unsigned)(acc[2*j]   & 0xffffffffull)) +
                       __uint_as_float((unsigned)(acc[2*j]   >> 32));
            float f1 = __uint_as_float((unsigned)(acc[2*j+1] & 0xffffffffull)) +
                       __uint_as_float((unsigned)(acc[2*j+1] >> 32));
            u[j] = ((unsigned long long)__float_as_uint(f1) << 32) | __float_as_uint(f0);
        }
        #pragma unroll
        for (int o = 16; o >= 2; o >>= 1) {
            #pragma unroll
            for (int j = 0; j < 3; j++) {
                unsigned long long v = __shfl_xor_sync(0xffffffffu, u[j], o);
                ADD2(u[j], u[j], v);
            }
        }
        if (lane < 2) {
            int slot = warp * 2 + lane;
            #pragma unroll
            for (int j = 0; j < 3; j++) {
                part[(TPB*NP + 2*j  )*32 + slot] = __uint_as_float((unsigned)(u[j] & 0xffffffffull));
                part[(TPB*NP + 2*j+1)*32 + slot] = __uint_as_float((unsigned)(u[j] >> 32));
            }
        }
    }
    // centroid norms
    if (tid < NE) {
        float s = 0.f;
        #pragma unroll
        for (int p = 0; p < NP; p++) { float c = cent_s[tid*NP + p]; s += c * c; }
        centn_s[tid] = s;
    }

    // -------- main loop: 16 chunks x 4 tokens --------
    #pragma unroll 1
    for (int c = 0; c < NCHUNK; c++) {
        int s = c & 1, ph = (c >> 1) & 1;
        MBAR_WAIT(mb + s * 8, ph);

        #pragma unroll
        for (int t = 0; t < STAGE_TOK; t++) {
            const ulonglong2* xp = (const ulonglong2*)
                (smem_c + XS_OFF + s * STAGE_BYTES + t * (HD*4) + warp * (SLICE*4));
            ulonglong2 xa = xp[lane];
            ulonglong2 xb = xp[lane + 32];

            unsigned long long acc[NP];
            #pragma unroll
            for (int p = 0; p < NP; p++) {
                acc[p] = 0ull;
                FMA2(acc[p], xa.x, cA[p].x); FMA2(acc[p], xa.y, cA[p].y);
                FMA2(acc[p], xb.x, cB[p].x); FMA2(acc[p], xb.y, cB[p].y);
            }
            unsigned long long u[3];
            #pragma unroll
            for (int j = 0; j < 3; j++) {
                float f0 = __uint_as_float((unsigned)(acc[2*j]   & 0xffffffffull)) +
                           __uint_as_float((unsigned)(acc[2*j]   >> 32));
                float f1 = __uint_as_float((unsigned)(acc[2*j+1] & 0xffffffffull)) +
                           __uint_as_float((unsigned)(acc[2*j+1] >> 32));
                u[j] = ((unsigned long long)__float_as_uint(f1) << 32) | __float_as_uint(f0);
            }
            #pragma unroll
            for (int o = 16; o >= 2; o >>= 1) {
                #pragma unroll
                for (int j = 0; j < 3; j++) {
                    unsigned long long v = __shfl_xor_sync(0xffffffffu, u[j], o);
                    ADD2(u[j], u[j], v);
                }
            }
            if (lane < 2) {
                int tok = c * STAGE_TOK + t;
                int slot = warp * 2 + lane;
                #pragma unroll
                for (int j = 0; j < 3; j++) {
                    part[(tok*NP + 2*j  )*32 + slot] = __uint_as_float((unsigned)(u[j] & 0xffffffffull));
                    part[(tok*NP + 2*j+1)*32 + slot] = __uint_as_float((unsigned)(u[j] >> 32));
                }
            }
        }
        __syncwarp();
        if (lane == 0) MBAR_ARRIVE(mb + 16 + s * 8);
    }

    __syncthreads();   // all partials visible

    // -------- epilogue: warp handles 4 tokens --------
    float mpj[NP];
    #pragma unroll
    for (int p = 0; p < NP; p++) {
        float v = part[(TPB*NP + p)*32 + lane];
        #pragma unroll
        for (int o = 16; o > 0; o >>= 1)
            v += __shfl_xor_sync(0xffffffffu, v, o);
        mpj[p] = v;
    }

    float* out_idx = out;
    float* out_tp  = out + (size_t)NTOK * TK;
    float* out_pr  = out + 2 * (size_t)NTOK * TK;

    #pragma unroll 1
    for (int t = 0; t < 4; t++) {
        const int ltok = warp * 4 + t;
        const int tok  = blockIdx.x * TPB + ltok;

        float pr[NP];
        #pragma unroll
        for (int p = 0; p < NP; p++) {
            float v = part[(ltok*NP + p)*32 + lane];
            #pragma unroll
            for (int o = 16; o > 0; o >>= 1)
                v += __shfl_xor_sync(0xffffffffu, v, o);
            pr[p] = v - mpj[p];
        }
        float pn = 0.f;
        #pragma unroll
        for (int p = 0; p < NP; p++) pn += pr[p] * pr[p];

        const int e0 = lane, e1 = lane + 32;
        float dot0 = 0.f, dot1 = 0.f;
        #pragma unroll
        for (int p = 0; p < NP; p++) {
            dot0 += pr[p] * cent_s[e0*NP + p];
            dot1 += pr[p] * cent_s[e1*NP + p];
        }
        float d20 = pn - 2.f*dot0 + centn_s[e0];
        float d21 = pn - 2.f*dot1 + centn_s[e1];
        float s0 = -sqrtf(fmaxf(d20, 0.f));
        float s1 = -sqrtf(fmaxf(d21, 0.f));

        float m = fmaxf(s0, s1);
        #pragma unroll
        for (int o = 16; o > 0; o >>= 1)
            m = fmaxf(m, __shfl_xor_sync(0xffffffffu, m, o));
        float ex0 = expf(s0 - m);
        float ex1 = expf(s1 - m);
        float sum = ex0 + ex1;
        #pragma unroll
        for (int o = 16; o > 0; o >>= 1)
            sum += __shfl_xor_sync(0xffffffffu, sum, o);
        float p0 = ex0 / sum;
        float p1 = ex1 / sum;

        out_pr[(size_t)tok*NE + e0] = p0;
        out_pr[(size_t)tok*NE + e1] = p1;

        // top-8 via 8-round warp argmax; tie-break = lower index
        unsigned long long k0 = ((unsigned long long)__float_as_uint(p0) << 32) | (unsigned)(NE-1 - e0);
        unsigned long long k1 = ((unsigned long long)__float_as_uint(p1) << 32) | (unsigned)(NE-1 - e1);
        float tsum = 0.f, myp = 0.f;
        int myi = 0;
        #pragma unroll
        for (int r = 0; r < TK; r++) {
            unsigned long long b = (k0 > k1) ? k0 : k1;
            #pragma unroll
            for (int o = 16; o > 0; o >>= 1) {
                unsigned long long v = __shfl_xor_sync(0xffffffffu, b, o);
                if (v > b) b = v;
            }
            int idx = NE-1 - (int)(b & 0xffull);
            float pv = __uint_as_float((unsigned)(b >> 32));
            tsum += pv;
            if (lane == r) { myp = pv; myi = idx; }
            if (idx == e0) k0 = 0ull;
            if (idx == e1) k1 = 0ull;
        }
        if (lane < TK) {
            out_idx[(size_t)tok*TK + lane] = (float)myi;
            out_tp [(size_t)tok*TK + lane] = myp / tsum;
        }
    }
}

extern "C" void kernel_launch(void* const* d_in, const int* in_sizes, int n_in,
                              void* d_out, int out_size)
{
    const float* x    = (const float*)d_in[0];
    const float* mean = (const float*)d_in[1];
    const float* comp = (const float*)d_in[2];
    const float* cent = (const float*)d_in[3];
    float* out = (float*)d_out;

    cudaFuncSetAttribute(kdtree_router_kernel,
                         cudaFuncAttributeMaxDynamicSharedMemorySize, SMEM_BYTES);
    kdtree_router_kernel<<<NTOK / TPB, NTHREADS, SMEM_BYTES>>>(x, mean, comp, cent, out);
}